// round 12
// baseline (speedup 1.0000x reference)
#include <cuda_runtime.h>
#include <cuda_fp16.h>
#include <cstdint>

using f16 = __half;

// Problem dims
constexpr int BATCH    = 8192;
constexpr int IN_SIZE  = 4096;
constexpr int HIDDEN   = 4096;
constexpr int OUT_SIZE = 1024;

// GEMM tiling (layers 1,2): CTA 128x128, warp tile 64x32 (2x4), BK=64, 2 CTAs/SM
constexpr int TM = 128;
constexpr int TN = 128;
constexpr int BK = 64;
constexpr int STAGES = 3;
constexpr int ROW_ELEMS  = 72;                    // 64 data + 8 pad f16 (144B pitch)
constexpr int A_ELEMS = TM * ROW_ELEMS;           // 9216
constexpr int B_ELEMS = TN * ROW_ELEMS;           // 9216
constexpr int STAGE_ELEMS = A_ELEMS + B_ELEMS;    // 18432
constexpr int SMEM_BYTES = STAGES * STAGE_ELEMS * 2;  // 110592 B -> 2 CTAs/SM

// layer-3 tiling: CTA 64x64, warp tile 32x16 (2x4), quarter-duration CTAs
constexpr int TM3 = 64;
constexpr int TN3 = 64;
constexpr int S3_ELEMS = (TM3 + TN3) * ROW_ELEMS;     // 9216
constexpr int SMEM3_BYTES = STAGES * S3_ELEMS * 2;    // 55296 B

// ---------------- static device scratch ----------------
__device__ f16 g_w1s[HIDDEN * IN_SIZE];
__device__ f16 g_w2s[HIDDEN * HIDDEN];
__device__ f16 g_w3s[OUT_SIZE * HIDDEN];
__device__ f16 g_a[BATCH * IN_SIZE];
__device__ f16 g_b[BATCH * HIDDEN];
__device__ float g_part[3 * 2048];
__device__ float g_sum[3];

// ---------------- PTX helpers ----------------
__device__ __forceinline__ uint32_t sptr(const void* p) {
    return (uint32_t)__cvta_generic_to_shared(p);
}
__device__ __forceinline__ void cp16(const f16* dst_smem, const f16* src_gmem) {
    uint32_t d = sptr(dst_smem);
    asm volatile("cp.async.cg.shared.global [%0], [%1], 16;\n" :: "r"(d), "l"(src_gmem));
}
__device__ __forceinline__ void ldsm4(uint32_t* r, uint32_t addr) {
    asm volatile("ldmatrix.sync.aligned.m8n8.x4.shared.b16 {%0,%1,%2,%3}, [%4];"
                 : "=r"(r[0]), "=r"(r[1]), "=r"(r[2]), "=r"(r[3]) : "r"(addr));
}
__device__ __forceinline__ void mma_f16(float* d, const uint32_t* a, const uint32_t* b) {
    asm volatile(
        "mma.sync.aligned.m16n8k16.row.col.f32.f16.f16.f32 "
        "{%0,%1,%2,%3}, {%4,%5,%6,%7}, {%8,%9}, {%0,%1,%2,%3};"
        : "+f"(d[0]), "+f"(d[1]), "+f"(d[2]), "+f"(d[3])
        : "r"(a[0]), "r"(a[1]), "r"(a[2]), "r"(a[3]), "r"(b[0]), "r"(b[1]));
}

// ---------------- shared quant helper ----------------
__device__ __forceinline__ void quant_signs(const float4* __restrict__ w4,
                                            __half2* __restrict__ ws2,
                                            int n4, int layer,
                                            int bid, int nblocks, int tid) {
    float s = 0.f;
    for (int i = bid * 256 + tid; i < n4; i += nblocks * 256) {
        float4 v = w4[i];
        s += fabsf(v.x) + fabsf(v.y) + fabsf(v.z) + fabsf(v.w);
        f16 s0 = __float2half((v.x > 0.f) ? 1.f : ((v.x < 0.f) ? -1.f : 0.f));
        f16 s1 = __float2half((v.y > 0.f) ? 1.f : ((v.y < 0.f) ? -1.f : 0.f));
        f16 s2 = __float2half((v.z > 0.f) ? 1.f : ((v.z < 0.f) ? -1.f : 0.f));
        f16 s3 = __float2half((v.w > 0.f) ? 1.f : ((v.w < 0.f) ? -1.f : 0.f));
        ws2[2 * i]     = __halves2half2(s0, s1);
        ws2[2 * i + 1] = __halves2half2(s2, s3);
    }
    __shared__ float red[256];
    red[tid] = s;
    __syncthreads();
    for (int o = 128; o > 0; o >>= 1) {
        if (tid < o) red[tid] += red[tid + o];
        __syncthreads();
    }
    if (tid == 0) g_part[layer * 2048 + bid] = red[0];
}

// ---------------- prep: sign(w1) + convert(x) fused ----------------
__global__ void prep1_kernel(const float4* __restrict__ w1,
                             __half2* __restrict__ w1s,
                             const float4* __restrict__ x4,
                             __half2* __restrict__ xh, int n4w, int n4x) {
    quant_signs(w1, w1s, n4w, 0, blockIdx.x, gridDim.x, threadIdx.x);
    for (int i = blockIdx.x * blockDim.x + threadIdx.x; i < n4x; i += gridDim.x * blockDim.x) {
        float4 v = x4[i];
        xh[2 * i]     = __halves2half2(__float2half(v.x), __float2half(v.y));
        xh[2 * i + 1] = __halves2half2(__float2half(v.z), __float2half(v.w));
    }
}

__global__ void finalize_one_kernel(int layer, int nparts) {
    __shared__ float red[1024];
    int t = threadIdx.x;
    float s = 0.f;
    for (int i = t; i < nparts; i += 1024) s += g_part[layer * 2048 + i];
    red[t] = s;
    __syncthreads();
    for (int o = 512; o > 0; o >>= 1) {
        if (t < o) red[t] += red[t + o];
        __syncthreads();
    }
    if (t == 0) g_sum[layer] = red[0];
}

// ---------------- GEMM (layers 1,2) + embedded next-layer weight quant ----------------
__global__ void __launch_bounds__(256, 2) gemm_bwn(
    const f16* __restrict__ A, const f16* __restrict__ Bs,
    const float* __restrict__ bias, const float* __restrict__ sumAbs, float invCnt,
    int K, int N, int NB,
    f16* __restrict__ oH,
    const float4* __restrict__ wsrc, __half2* __restrict__ wdst, int wn4, int wlayer) {
    extern __shared__ f16 smem[];
    const int tid  = threadIdx.x;

    if (blockIdx.x >= NB) {  // embedded prep path
        quant_signs(wsrc, wdst, wn4, wlayer, blockIdx.y, gridDim.y, tid);
        return;
    }

    const int lane = tid & 31;
    const int warp = tid >> 5;
    const int wm = warp & 1;   // 2 warp-rows of 64
    const int wn = warp >> 1;  // 4 warp-cols of 32
    const int bm = blockIdx.y, bn = blockIdx.x;
    const int KT = K / BK;

    const f16* gA = A  + (size_t)bm * TM * K;
    const f16* gB = Bs + (size_t)bn * TN * K;

    const int crow = tid >> 3;        // 0..31
    const int ccol = (tid & 7) * 8;   // 16B chunks

    auto issue = [&](int kt, int stage) {
        f16* sa = smem + stage * STAGE_ELEMS;
        f16* sb = sa + A_ELEMS;
        const int kof = kt * BK;
#pragma unroll
        for (int rr = 0; rr < 4; rr++) {
            const int row = rr * 32 + crow;
            cp16(sa + row * ROW_ELEMS + ccol, gA + (size_t)row * K + kof + ccol);
            cp16(sb + row * ROW_ELEMS + ccol, gB + (size_t)row * K + kof + ccol);
        }
    };

    float acc[4][4][4];
#pragma unroll
    for (int i = 0; i < 4; i++)
#pragma unroll
        for (int j = 0; j < 4; j++)
#pragma unroll
            for (int v = 0; v < 4; v++) acc[i][j][v] = 0.f;

    const int a_off = (wm * 64 + (lane & 15)) * ROW_ELEMS + (lane >> 4) * 8;
    const int b_off = (wn * 32 + ((lane >> 4) & 1) * 8 + (lane & 7)) * ROW_ELEMS
                    + ((lane >> 3) & 1) * 8;

    issue(0, 0);
    asm volatile("cp.async.commit_group;" ::: "memory");
    issue(1, 1);
    asm volatile("cp.async.commit_group;" ::: "memory");

    for (int kt = 0; kt < KT; kt++) {
        const int stage = kt % STAGES;
        asm volatile("cp.async.wait_group 1;" ::: "memory");
        __syncthreads();
        const int kn = kt + 2;
        if (kn < KT) issue(kn, kn % STAGES);
        asm volatile("cp.async.commit_group;" ::: "memory");

        const f16* sA = smem + stage * STAGE_ELEMS;
        const f16* sB = sA + A_ELEMS;
#pragma unroll
        for (int ks = 0; ks < 4; ks++) {
            const int kc = ks * 16;
            uint32_t af[4][4], bf[4][2];
#pragma unroll
            for (int i = 0; i < 4; i++)
                ldsm4(af[i], sptr(sA + a_off + (i & 1) * 16 * ROW_ELEMS
                                     + (i >> 1) * 32 * ROW_ELEMS + kc));
#pragma unroll
            for (int jj = 0; jj < 2; jj++) {
                uint32_t r[4];
                ldsm4(r, sptr(sB + b_off + jj * 16 * ROW_ELEMS + kc));
                bf[2 * jj][0] = r[0]; bf[2 * jj][1] = r[1];
                bf[2 * jj + 1][0] = r[2]; bf[2 * jj + 1][1] = r[3];
            }
#pragma unroll
            for (int i = 0; i < 4; i++)
#pragma unroll
                for (int j = 0; j < 4; j++)
                    mma_f16(acc[i][j], af[i], bf[j]);
        }
    }

    // epilogue: relu -> f16
    const float alpha = __ldg(sumAbs) * invCnt;
    const int r0 = bm * TM + wm * 64 + (lane >> 2);
    const int c0 = bn * TN + wn * 32 + (lane & 3) * 2;
#pragma unroll
    for (int i = 0; i < 4; i++) {
#pragma unroll
        for (int j = 0; j < 4; j++) {
            int row = r0 + (i & 1) * 16 + (i >> 1) * 32;
            int col = c0 + j * 8;
            float bx = __ldg(bias + col), by = __ldg(bias + col + 1);
            float v00 = fmaxf(acc[i][j][0] * alpha + bx, 0.f);
            float v01 = fmaxf(acc[i][j][1] * alpha + by, 0.f);
            float v10 = fmaxf(acc[i][j][2] * alpha + bx, 0.f);
            float v11 = fmaxf(acc[i][j][3] * alpha + by, 0.f);
            size_t i0 = (size_t)row * N + col;
            size_t i1 = (size_t)(row + 8) * N + col;
            *reinterpret_cast<__half2*>(oH + i0) =
                __halves2half2(__float2half(v00), __float2half(v01));
            *reinterpret_cast<__half2*>(oH + i1) =
                __halves2half2(__float2half(v10), __float2half(v11));
        }
    }
}

// ---------------- GEMM layer 3: 64x64 CTA tiles (fine tail), sigmoid -> f32 ----------------
__global__ void __launch_bounds__(256, 2) gemm_l3(
    const f16* __restrict__ A, const f16* __restrict__ Bs,
    const float* __restrict__ bias, const float* __restrict__ sumAbs, float invCnt,
    int K, int N, float* __restrict__ oF) {
    extern __shared__ f16 smem[];
    const int tid  = threadIdx.x;
    const int lane = tid & 31;
    const int warp = tid >> 5;
    const int wm = warp & 1;   // 2 warp-rows of 32
    const int wn = warp >> 1;  // 4 warp-cols of 16
    const int bm = blockIdx.y, bn = blockIdx.x;
    const int KT = K / BK;

    const f16* gA = A  + (size_t)bm * TM3 * K;
    const f16* gB = Bs + (size_t)bn * TN3 * K;

    const int crow = tid >> 3;        // 0..31
    const int ccol = (tid & 7) * 8;

    auto issue = [&](int kt, int stage) {
        f16* sa = smem + stage * S3_ELEMS;
        f16* sb = sa + TM3 * ROW_ELEMS;
        const int kof = kt * BK;
#pragma unroll
        for (int rr = 0; rr < 2; rr++) {
            const int row = rr * 32 + crow;
            cp16(sa + row * ROW_ELEMS + ccol, gA + (size_t)row * K + kof + ccol);
            cp16(sb + row * ROW_ELEMS + ccol, gB + (size_t)row * K + kof + ccol);
        }
    };

    float acc[2][2][4];
#pragma unroll
    for (int i = 0; i < 2; i++)
#pragma unroll
        for (int j = 0; j < 2; j++)
#pragma unroll
            for (int v = 0; v < 4; v++) acc[i][j][v] = 0.f;

    const int a_off = (wm * 32 + (lane & 15)) * ROW_ELEMS + (lane >> 4) * 8;
    const int b_off = (wn * 16 + ((lane >> 4) & 1) * 8 + (lane & 7)) * ROW_ELEMS
                    + ((lane >> 3) & 1) * 8;

    issue(0, 0);
    asm volatile("cp.async.commit_group;" ::: "memory");
    issue(1, 1);
    asm volatile("cp.async.commit_group;" ::: "memory");

    for (int kt = 0; kt < KT; kt++) {
        const int stage = kt % STAGES;
        asm volatile("cp.async.wait_group 1;" ::: "memory");
        __syncthreads();
        const int kn = kt + 2;
        if (kn < KT) issue(kn, kn % STAGES);
        asm volatile("cp.async.commit_group;" ::: "memory");

        const f16* sA = smem + stage * S3_ELEMS;
        const f16* sB = sA + TM3 * ROW_ELEMS;
#pragma unroll
        for (int ks = 0; ks < 4; ks++) {
            const int kc = ks * 16;
            uint32_t af[2][4], bf[2][2];
#pragma unroll
            for (int i = 0; i < 2; i++)
                ldsm4(af[i], sptr(sA + a_off + i * 16 * ROW_ELEMS + kc));
            {
                uint32_t r[4];
                ldsm4(r, sptr(sB + b_off + kc));
                bf[0][0] = r[0]; bf[0][1] = r[1];
                bf[1][0] = r[2]; bf[1][1] = r[3];
            }
#pragma unroll
            for (int i = 0; i < 2; i++)
#pragma unroll
                for (int j = 0; j < 2; j++)
                    mma_f16(acc[i][j], af[i], bf[j]);
        }
    }

    // epilogue: sigmoid -> f32
    const float alpha = __ldg(sumAbs) * invCnt;
    const int r0 = bm * TM3 + wm * 32 + (lane >> 2);
    const int c0 = bn * TN3 + wn * 16 + (lane & 3) * 2;
#pragma unroll
    for (int i = 0; i < 2; i++) {
#pragma unroll
        for (int j = 0; j < 2; j++) {
            int row = r0 + i * 16;
            int col = c0 + j * 8;
            float bx = __ldg(bias + col), by = __ldg(bias + col + 1);
            float v00 = acc[i][j][0] * alpha + bx;
            float v01 = acc[i][j][1] * alpha + by;
            float v10 = acc[i][j][2] * alpha + bx;
            float v11 = acc[i][j][3] * alpha + by;
            float2 s0, s1;
            s0.x = 1.f / (1.f + __expf(-v00));
            s0.y = 1.f / (1.f + __expf(-v01));
            s1.x = 1.f / (1.f + __expf(-v10));
            s1.y = 1.f / (1.f + __expf(-v11));
            *reinterpret_cast<float2*>(oF + (size_t)row * N + col)       = s0;
            *reinterpret_cast<float2*>(oF + (size_t)(row + 8) * N + col) = s1;
        }
    }
}

// ---------------- host launch ----------------
extern "C" void kernel_launch(void* const* d_in, const int* in_sizes, int n_in,
                              void* d_out, int out_size) {
    const float* x  = (const float*)d_in[0];
    const float* w1 = (const float*)d_in[1];
    const float* b1 = (const float*)d_in[2];
    const float* w2 = (const float*)d_in[3];
    const float* b2 = (const float*)d_in[4];
    const float* w3 = (const float*)d_in[5];
    const float* b3 = (const float*)d_in[6];

    void *pw1, *pw2, *pw3, *pa, *pb, *psum;
    cudaGetSymbolAddress(&pw1, g_w1s);
    cudaGetSymbolAddress(&pw2, g_w2s);
    cudaGetSymbolAddress(&pw3, g_w3s);
    cudaGetSymbolAddress(&pa, g_a);
    cudaGetSymbolAddress(&pb, g_b);
    cudaGetSymbolAddress(&psum, g_sum);
    float* sum = (float*)psum;

    cudaFuncSetAttribute(gemm_bwn, cudaFuncAttributeMaxDynamicSharedMemorySize, SMEM_BYTES);
    cudaFuncSetAttribute(gemm_l3, cudaFuncAttributeMaxDynamicSharedMemorySize, SMEM3_BYTES);

    // serial prefix: sign(w1) + convert(x), then finalize sum0
    prep1_kernel<<<2048, 256>>>((const float4*)w1, (__half2*)pw1,
                                (const float4*)x, (__half2*)pa,
                                HIDDEN * IN_SIZE / 4, BATCH * IN_SIZE / 4);
    finalize_one_kernel<<<1, 1024>>>(0, 2048);

    // GEMM1 (+ embedded sign(w2))
    gemm_bwn<<<dim3(HIDDEN / TN + 1, BATCH / TM), 256, SMEM_BYTES>>>(
        (const f16*)pa, (const f16*)pw1, b1, sum + 0,
        1.0f / ((float)HIDDEN * (float)IN_SIZE),
        IN_SIZE, HIDDEN, HIDDEN / TN, (f16*)pb,
        (const float4*)w2, (__half2*)pw2, HIDDEN * HIDDEN / 4, 1);
    finalize_one_kernel<<<1, 1024>>>(1, BATCH / TM);

    // GEMM2 (+ embedded sign(w3))
    gemm_bwn<<<dim3(HIDDEN / TN + 1, BATCH / TM), 256, SMEM_BYTES>>>(
        (const f16*)pb, (const f16*)pw2, b2, sum + 1,
        1.0f / ((float)HIDDEN * (float)HIDDEN),
        HIDDEN, HIDDEN, HIDDEN / TN, (f16*)pa,
        (const float4*)w3, (__half2*)pw3, OUT_SIZE * HIDDEN / 4, 2);
    finalize_one_kernel<<<1, 1024>>>(2, BATCH / TM);

    // GEMM3: fine 64x64 tiles for low tail quantization
    gemm_l3<<<dim3(OUT_SIZE / TN3, BATCH / TM3), 256, SMEM3_BYTES>>>(
        (const f16*)pa, (const f16*)pw3, b3, sum + 2,
        1.0f / ((float)OUT_SIZE * (float)HIDDEN),
        HIDDEN, OUT_SIZE, (float*)d_out);
}

// round 13
// speedup vs baseline: 1.0226x; 1.0226x over previous
#include <cuda_runtime.h>
#include <cuda_fp16.h>
#include <cstdint>

using f16 = __half;

// Problem dims
constexpr int BATCH    = 8192;
constexpr int IN_SIZE  = 4096;
constexpr int HIDDEN   = 4096;
constexpr int OUT_SIZE = 1024;

// GEMM tiling: CTA 128x128, warp tile 64x32 (2x4), BK=64, 2 CTAs/SM
constexpr int TM = 128;
constexpr int TN = 128;
constexpr int BK = 64;
constexpr int STAGES = 3;
constexpr int ROW_ELEMS  = 72;                    // 64 data + 8 pad f16 (144B pitch)
constexpr int A_ELEMS = TM * ROW_ELEMS;           // 9216
constexpr int B_ELEMS = TN * ROW_ELEMS;           // 9216
constexpr int STAGE_ELEMS = A_ELEMS + B_ELEMS;    // 18432
constexpr int SMEM_BYTES = STAGES * STAGE_ELEMS * 2;  // 110592 B -> 2 CTAs/SM

// ---------------- static device scratch ----------------
__device__ f16 g_w1s[HIDDEN * IN_SIZE];
__device__ f16 g_w2s[HIDDEN * HIDDEN];
__device__ f16 g_w3s[OUT_SIZE * HIDDEN];
__device__ f16 g_a[BATCH * IN_SIZE];
__device__ f16 g_b[BATCH * HIDDEN];
__device__ float g_part[3 * 2048];

// ---------------- PTX helpers ----------------
__device__ __forceinline__ uint32_t sptr(const void* p) {
    return (uint32_t)__cvta_generic_to_shared(p);
}
__device__ __forceinline__ void cp16(const f16* dst_smem, const f16* src_gmem) {
    uint32_t d = sptr(dst_smem);
    asm volatile("cp.async.cg.shared.global [%0], [%1], 16;\n" :: "r"(d), "l"(src_gmem));
}
__device__ __forceinline__ void ldsm4(uint32_t* r, uint32_t addr) {
    asm volatile("ldmatrix.sync.aligned.m8n8.x4.shared.b16 {%0,%1,%2,%3}, [%4];"
                 : "=r"(r[0]), "=r"(r[1]), "=r"(r[2]), "=r"(r[3]) : "r"(addr));
}
__device__ __forceinline__ void mma_f16(float* d, const uint32_t* a, const uint32_t* b) {
    asm volatile(
        "mma.sync.aligned.m16n8k16.row.col.f32.f16.f16.f32 "
        "{%0,%1,%2,%3}, {%4,%5,%6,%7}, {%8,%9}, {%0,%1,%2,%3};"
        : "+f"(d[0]), "+f"(d[1]), "+f"(d[2]), "+f"(d[3])
        : "r"(a[0]), "r"(a[1]), "r"(a[2]), "r"(a[3]), "r"(b[0]), "r"(b[1]));
}

// ---------------- shared quant helper (sign -> f16, block partial |w| sums) ----------------
__device__ __forceinline__ void quant_signs(const float4* __restrict__ w4,
                                            __half2* __restrict__ ws2,
                                            int n4, int layer,
                                            int bid, int nblocks, int tid) {
    float s = 0.f;
    for (int i = bid * 256 + tid; i < n4; i += nblocks * 256) {
        float4 v = w4[i];
        s += fabsf(v.x) + fabsf(v.y) + fabsf(v.z) + fabsf(v.w);
        f16 s0 = __float2half((v.x > 0.f) ? 1.f : ((v.x < 0.f) ? -1.f : 0.f));
        f16 s1 = __float2half((v.y > 0.f) ? 1.f : ((v.y < 0.f) ? -1.f : 0.f));
        f16 s2 = __float2half((v.z > 0.f) ? 1.f : ((v.z < 0.f) ? -1.f : 0.f));
        f16 s3 = __float2half((v.w > 0.f) ? 1.f : ((v.w < 0.f) ? -1.f : 0.f));
        ws2[2 * i]     = __halves2half2(s0, s1);
        ws2[2 * i + 1] = __halves2half2(s2, s3);
    }
    __shared__ float red[256];
    red[tid] = s;
    __syncthreads();
    for (int o = 128; o > 0; o >>= 1) {
        if (tid < o) red[tid] += red[tid + o];
        __syncthreads();
    }
    if (tid == 0) g_part[layer * 2048 + bid] = red[0];
}

// ---------------- prep: sign(w1) + convert(x) fused ----------------
__global__ void prep1_kernel(const float4* __restrict__ w1,
                             __half2* __restrict__ w1s,
                             const float4* __restrict__ x4,
                             __half2* __restrict__ xh, int n4w, int n4x) {
    quant_signs(w1, w1s, n4w, 0, blockIdx.x, gridDim.x, threadIdx.x);
    for (int i = blockIdx.x * blockDim.x + threadIdx.x; i < n4x; i += gridDim.x * blockDim.x) {
        float4 v = x4[i];
        xh[2 * i]     = __halves2half2(__float2half(v.x), __float2half(v.y));
        xh[2 * i + 1] = __halves2half2(__float2half(v.z), __float2half(v.w));
    }
}

// deterministic in-CTA reduction of g_part[layer][0..nparts) -> alpha
// (identical order in every CTA -> identical alpha)
__device__ __forceinline__ float reduce_alpha(float* red256, int layer, int nparts,
                                              float invCnt, int tid) {
    float s = 0.f;
    for (int i = tid; i < nparts; i += 256) s += g_part[layer * 2048 + i];
    red256[tid] = s;
    __syncthreads();
    for (int o = 128; o > 0; o >>= 1) {
        if (tid < o) red256[tid] += red256[tid + o];
        __syncthreads();
    }
    float a = red256[0] * invCnt;
    __syncthreads();
    return a;
}

// ---------------- fused binarized GEMM + embedded next-layer weight quant ----------------
// EPI0: relu -> f16 ; EPI1: sigmoid -> f32
template <int EPI>
__global__ void __launch_bounds__(256, 2) gemm_bwn(
    const f16* __restrict__ A, const f16* __restrict__ Bs,
    const float* __restrict__ bias, int sumLayer, int sumParts, float invCnt,
    int K, int N, int NB,
    f16* __restrict__ oH, float* __restrict__ oF,
    const float4* __restrict__ wsrc, __half2* __restrict__ wdst, int wn4, int wlayer) {
    extern __shared__ f16 smem[];
    const int tid  = threadIdx.x;

    if (blockIdx.x >= NB) {  // embedded prep path
        quant_signs(wsrc, wdst, wn4, wlayer, blockIdx.y, gridDim.y, tid);
        return;
    }

    const int lane = tid & 31;
    const int warp = tid >> 5;
    const int wm = warp & 1;   // 2 warp-rows of 64
    const int wn = warp >> 1;  // 4 warp-cols of 32
    const int bm = blockIdx.y, bn = blockIdx.x;
    const int KT = K / BK;

    const f16* gA = A  + (size_t)bm * TM * K;
    const f16* gB = Bs + (size_t)bn * TN * K;

    const int crow = tid >> 3;        // 0..31
    const int ccol = (tid & 7) * 8;   // 16B chunks

    auto issue = [&](int kt, int stage) {
        f16* sa = smem + stage * STAGE_ELEMS;
        f16* sb = sa + A_ELEMS;
        const int kof = kt * BK;
#pragma unroll
        for (int rr = 0; rr < 4; rr++) {
            const int row = rr * 32 + crow;
            cp16(sa + row * ROW_ELEMS + ccol, gA + (size_t)row * K + kof + ccol);
            cp16(sb + row * ROW_ELEMS + ccol, gB + (size_t)row * K + kof + ccol);
        }
    };

    float acc[4][4][4];
#pragma unroll
    for (int i = 0; i < 4; i++)
#pragma unroll
        for (int j = 0; j < 4; j++)
#pragma unroll
            for (int v = 0; v < 4; v++) acc[i][j][v] = 0.f;

    const int a_off = (wm * 64 + (lane & 15)) * ROW_ELEMS + (lane >> 4) * 8;
    const int b_off = (wn * 32 + ((lane >> 4) & 1) * 8 + (lane & 7)) * ROW_ELEMS
                    + ((lane >> 3) & 1) * 8;

    issue(0, 0);
    asm volatile("cp.async.commit_group;" ::: "memory");
    issue(1, 1);
    asm volatile("cp.async.commit_group;" ::: "memory");

    for (int kt = 0; kt < KT; kt++) {
        const int stage = kt % STAGES;
        asm volatile("cp.async.wait_group 1;" ::: "memory");
        __syncthreads();
        const int kn = kt + 2;
        if (kn < KT) issue(kn, kn % STAGES);
        asm volatile("cp.async.commit_group;" ::: "memory");

        const f16* sA = smem + stage * STAGE_ELEMS;
        const f16* sB = sA + A_ELEMS;
#pragma unroll
        for (int ks = 0; ks < 4; ks++) {
            const int kc = ks * 16;
            uint32_t af[4][4], bf[4][2];
#pragma unroll
            for (int i = 0; i < 4; i++)
                ldsm4(af[i], sptr(sA + a_off + (i & 1) * 16 * ROW_ELEMS
                                     + (i >> 1) * 32 * ROW_ELEMS + kc));
#pragma unroll
            for (int jj = 0; jj < 2; jj++) {
                uint32_t r[4];
                ldsm4(r, sptr(sB + b_off + jj * 16 * ROW_ELEMS + kc));
                bf[2 * jj][0] = r[0]; bf[2 * jj][1] = r[1];
                bf[2 * jj + 1][0] = r[2]; bf[2 * jj + 1][1] = r[3];
            }
#pragma unroll
            for (int i = 0; i < 4; i++)
#pragma unroll
                for (int j = 0; j < 4; j++)
                    mma_f16(acc[i][j], af[i], bf[j]);
        }
    }

    // ---------------- epilogue (alpha reduced in-CTA, deterministic) ----------------
    asm volatile("cp.async.wait_group 0;" ::: "memory");
    __syncthreads();
    const float alpha = reduce_alpha(reinterpret_cast<float*>(smem), sumLayer,
                                     sumParts, invCnt, tid);
    const int r0 = bm * TM + wm * 64 + (lane >> 2);
    const int c0 = bn * TN + wn * 32 + (lane & 3) * 2;
#pragma unroll
    for (int i = 0; i < 4; i++) {
#pragma unroll
        for (int j = 0; j < 4; j++) {
            int row = r0 + (i & 1) * 16 + (i >> 1) * 32;
            int col = c0 + j * 8;
            float bx = __ldg(bias + col), by = __ldg(bias + col + 1);
            float v00 = acc[i][j][0] * alpha + bx;
            float v01 = acc[i][j][1] * alpha + by;
            float v10 = acc[i][j][2] * alpha + bx;
            float v11 = acc[i][j][3] * alpha + by;
            if (EPI == 0) {
                v00 = fmaxf(v00, 0.f); v01 = fmaxf(v01, 0.f);
                v10 = fmaxf(v10, 0.f); v11 = fmaxf(v11, 0.f);
                size_t i0 = (size_t)row * N + col;
                size_t i1 = (size_t)(row + 8) * N + col;
                *reinterpret_cast<__half2*>(oH + i0) =
                    __halves2half2(__float2half(v00), __float2half(v01));
                *reinterpret_cast<__half2*>(oH + i1) =
                    __halves2half2(__float2half(v10), __float2half(v11));
            } else {
                float2 s0, s1;
                s0.x = 1.f / (1.f + __expf(-v00));
                s0.y = 1.f / (1.f + __expf(-v01));
                s1.x = 1.f / (1.f + __expf(-v10));
                s1.y = 1.f / (1.f + __expf(-v11));
                *reinterpret_cast<float2*>(oF + (size_t)row * N + col)       = s0;
                *reinterpret_cast<float2*>(oF + (size_t)(row + 8) * N + col) = s1;
            }
        }
    }
}

// ---------------- host launch ----------------
extern "C" void kernel_launch(void* const* d_in, const int* in_sizes, int n_in,
                              void* d_out, int out_size) {
    const float* x  = (const float*)d_in[0];
    const float* w1 = (const float*)d_in[1];
    const float* b1 = (const float*)d_in[2];
    const float* w2 = (const float*)d_in[3];
    const float* b2 = (const float*)d_in[4];
    const float* w3 = (const float*)d_in[5];
    const float* b3 = (const float*)d_in[6];

    void *pw1, *pw2, *pw3, *pa, *pb;
    cudaGetSymbolAddress(&pw1, g_w1s);
    cudaGetSymbolAddress(&pw2, g_w2s);
    cudaGetSymbolAddress(&pw3, g_w3s);
    cudaGetSymbolAddress(&pa, g_a);
    cudaGetSymbolAddress(&pb, g_b);

    cudaFuncSetAttribute(gemm_bwn<0>, cudaFuncAttributeMaxDynamicSharedMemorySize, SMEM_BYTES);
    cudaFuncSetAttribute(gemm_bwn<1>, cudaFuncAttributeMaxDynamicSharedMemorySize, SMEM_BYTES);

    // serial prefix: sign(w1) + convert(x); partials in g_part[0][0..2048)
    prep1_kernel<<<2048, 256>>>((const float4*)w1, (__half2*)pw1,
                                (const float4*)x, (__half2*)pa,
                                HIDDEN * IN_SIZE / 4, BATCH * IN_SIZE / 4);

    // GEMM1 (+ embedded sign(w2): 64 blocks at bn==32 write g_part[1][0..64))
    gemm_bwn<0><<<dim3(HIDDEN / TN + 1, BATCH / TM), 256, SMEM_BYTES>>>(
        (const f16*)pa, (const f16*)pw1, b1, 0, 2048,
        1.0f / ((float)HIDDEN * (float)IN_SIZE),
        IN_SIZE, HIDDEN, HIDDEN / TN, (f16*)pb, nullptr,
        (const float4*)w2, (__half2*)pw2, HIDDEN * HIDDEN / 4, 1);

    // GEMM2 (+ embedded sign(w3) -> g_part[2][0..64))
    gemm_bwn<0><<<dim3(HIDDEN / TN + 1, BATCH / TM), 256, SMEM_BYTES>>>(
        (const f16*)pb, (const f16*)pw2, b2, 1, BATCH / TM,
        1.0f / ((float)HIDDEN * (float)HIDDEN),
        HIDDEN, HIDDEN, HIDDEN / TN, (f16*)pa, nullptr,
        (const float4*)w3, (__half2*)pw3, OUT_SIZE * HIDDEN / 4, 2);

    // GEMM3 (no embedded prep)
    gemm_bwn<1><<<dim3(OUT_SIZE / TN, BATCH / TM), 256, SMEM_BYTES>>>(
        (const f16*)pa, (const f16*)pw3, b3, 2, BATCH / TM,
        1.0f / ((float)OUT_SIZE * (float)HIDDEN),
        HIDDEN, OUT_SIZE, OUT_SIZE / TN, nullptr, (float*)d_out,
        nullptr, nullptr, 0, 0);
}

// round 14
// speedup vs baseline: 1.0228x; 1.0002x over previous
#include <cuda_runtime.h>
#include <cuda_fp16.h>
#include <cstdint>

using f16 = __half;

// Problem dims
constexpr int BATCH    = 8192;
constexpr int IN_SIZE  = 4096;
constexpr int HIDDEN   = 4096;
constexpr int OUT_SIZE = 1024;

// GEMM tiling: CTA 128x128, warp tile 64x32 (2x4), BK=64, 2 CTAs/SM
constexpr int TM = 128;
constexpr int TN = 128;
constexpr int BK = 64;
constexpr int STAGES = 3;
constexpr int ROW_ELEMS  = 72;                    // 64 data + 8 pad f16 (144B pitch)
constexpr int A_ELEMS = TM * ROW_ELEMS;           // 9216
constexpr int B_ELEMS = TN * ROW_ELEMS;           // 9216
constexpr int STAGE_ELEMS = A_ELEMS + B_ELEMS;    // 18432
constexpr int SMEM_BYTES = STAGES * STAGE_ELEMS * 2;  // 110592 B -> 2 CTAs/SM

// ---------------- static device scratch ----------------
__device__ f16 g_w1s[HIDDEN * IN_SIZE];
__device__ f16 g_w2s[HIDDEN * HIDDEN];
__device__ f16 g_w3s[OUT_SIZE * HIDDEN];
__device__ f16 g_a[BATCH * IN_SIZE];
__device__ f16 g_b[BATCH * HIDDEN];
__device__ float g_part[3 * 2048];

// ---------------- PTX helpers ----------------
__device__ __forceinline__ uint32_t sptr(const void* p) {
    return (uint32_t)__cvta_generic_to_shared(p);
}
__device__ __forceinline__ void cp16(const f16* dst_smem, const f16* src_gmem) {
    uint32_t d = sptr(dst_smem);
    asm volatile("cp.async.cg.shared.global [%0], [%1], 16;\n" :: "r"(d), "l"(src_gmem));
}
__device__ __forceinline__ void ldsm4(uint32_t* r, uint32_t addr) {
    asm volatile("ldmatrix.sync.aligned.m8n8.x4.shared.b16 {%0,%1,%2,%3}, [%4];"
                 : "=r"(r[0]), "=r"(r[1]), "=r"(r[2]), "=r"(r[3]) : "r"(addr));
}
__device__ __forceinline__ void mma_f16(float* d, const uint32_t* a, const uint32_t* b) {
    asm volatile(
        "mma.sync.aligned.m16n8k16.row.col.f32.f16.f16.f32 "
        "{%0,%1,%2,%3}, {%4,%5,%6,%7}, {%8,%9}, {%0,%1,%2,%3};"
        : "+f"(d[0]), "+f"(d[1]), "+f"(d[2]), "+f"(d[3])
        : "r"(a[0]), "r"(a[1]), "r"(a[2]), "r"(a[3]), "r"(b[0]), "r"(b[1]));
}

// ---------------- shared quant helper (sign -> f16, block partial |w| sums) ----------------
__device__ __forceinline__ void quant_signs(const float4* __restrict__ w4,
                                            __half2* __restrict__ ws2,
                                            int n4, int layer,
                                            int bid, int nblocks, int tid) {
    float s = 0.f;
    for (int i = bid * 256 + tid; i < n4; i += nblocks * 256) {
        float4 v = w4[i];
        s += fabsf(v.x) + fabsf(v.y) + fabsf(v.z) + fabsf(v.w);
        f16 s0 = __float2half((v.x > 0.f) ? 1.f : ((v.x < 0.f) ? -1.f : 0.f));
        f16 s1 = __float2half((v.y > 0.f) ? 1.f : ((v.y < 0.f) ? -1.f : 0.f));
        f16 s2 = __float2half((v.z > 0.f) ? 1.f : ((v.z < 0.f) ? -1.f : 0.f));
        f16 s3 = __float2half((v.w > 0.f) ? 1.f : ((v.w < 0.f) ? -1.f : 0.f));
        ws2[2 * i]     = __halves2half2(s0, s1);
        ws2[2 * i + 1] = __halves2half2(s2, s3);
    }
    __shared__ float red[256];
    red[tid] = s;
    __syncthreads();
    for (int o = 128; o > 0; o >>= 1) {
        if (tid < o) red[tid] += red[tid + o];
        __syncthreads();
    }
    if (tid == 0) g_part[layer * 2048 + bid] = red[0];
}

// ---------------- prep: sign(w1) + convert(x) fused (1024 partial blocks) ----------------
__global__ void prep1_kernel(const float4* __restrict__ w1,
                             __half2* __restrict__ w1s,
                             const float4* __restrict__ x4,
                             __half2* __restrict__ xh, int n4w, int n4x) {
    quant_signs(w1, w1s, n4w, 0, blockIdx.x, gridDim.x, threadIdx.x);
    for (int i = blockIdx.x * blockDim.x + threadIdx.x; i < n4x; i += gridDim.x * blockDim.x) {
        float4 v = x4[i];
        xh[2 * i]     = __halves2half2(__float2half(v.x), __float2half(v.y));
        xh[2 * i + 1] = __halves2half2(__float2half(v.z), __float2half(v.w));
    }
}

// deterministic in-CTA reduction of g_part[layer][0..nparts) -> alpha
// (identical order in every CTA -> identical alpha everywhere)
__device__ __forceinline__ float reduce_alpha(float* red256, int layer, int nparts,
                                              float invCnt, int tid) {
    float s = 0.f;
    for (int i = tid; i < nparts; i += 256) s += g_part[layer * 2048 + i];
    red256[tid] = s;
    __syncthreads();
    for (int o = 128; o > 0; o >>= 1) {
        if (tid < o) red256[tid] += red256[tid + o];
        __syncthreads();
    }
    float a = red256[0] * invCnt;
    __syncthreads();
    return a;
}

// ---------------- fused binarized GEMM + embedded next-layer weight quant ----------------
// EPI0: relu -> f16 ; EPI1: sigmoid -> f32
template <int EPI>
__global__ void __launch_bounds__(256, 2) gemm_bwn(
    const f16* __restrict__ A, const f16* __restrict__ Bs,
    const float* __restrict__ bias, int sumLayer, int sumParts, float invCnt,
    int K, int N, int NB,
    f16* __restrict__ oH, float* __restrict__ oF,
    const float4* __restrict__ wsrc, __half2* __restrict__ wdst, int wn4, int wlayer) {
    extern __shared__ f16 smem[];
    const int tid  = threadIdx.x;

    if (blockIdx.x >= NB) {  // embedded prep path (next layer's weights)
        quant_signs(wsrc, wdst, wn4, wlayer, blockIdx.y, gridDim.y, tid);
        return;
    }

    const int lane = tid & 31;
    const int warp = tid >> 5;
    const int wm = warp & 1;   // 2 warp-rows of 64
    const int wn = warp >> 1;  // 4 warp-cols of 32
    const int bm = blockIdx.y, bn = blockIdx.x;
    const int KT = K / BK;

    const f16* gA = A  + (size_t)bm * TM * K;
    const f16* gB = Bs + (size_t)bn * TN * K;

    const int crow = tid >> 3;        // 0..31
    const int ccol = (tid & 7) * 8;   // 16B chunks

    auto issue = [&](int kt, int stage) {
        f16* sa = smem + stage * STAGE_ELEMS;
        f16* sb = sa + A_ELEMS;
        const int kof = kt * BK;
#pragma unroll
        for (int rr = 0; rr < 4; rr++) {
            const int row = rr * 32 + crow;
            cp16(sa + row * ROW_ELEMS + ccol, gA + (size_t)row * K + kof + ccol);
            cp16(sb + row * ROW_ELEMS + ccol, gB + (size_t)row * K + kof + ccol);
        }
    };

    float acc[4][4][4];
#pragma unroll
    for (int i = 0; i < 4; i++)
#pragma unroll
        for (int j = 0; j < 4; j++)
#pragma unroll
            for (int v = 0; v < 4; v++) acc[i][j][v] = 0.f;

    const int a_off = (wm * 64 + (lane & 15)) * ROW_ELEMS + (lane >> 4) * 8;
    const int b_off = (wn * 32 + ((lane >> 4) & 1) * 8 + (lane & 7)) * ROW_ELEMS
                    + ((lane >> 3) & 1) * 8;

    issue(0, 0);
    asm volatile("cp.async.commit_group;" ::: "memory");
    issue(1, 1);
    asm volatile("cp.async.commit_group;" ::: "memory");

    for (int kt = 0; kt < KT; kt++) {
        const int stage = kt % STAGES;
        asm volatile("cp.async.wait_group 1;" ::: "memory");
        __syncthreads();
        const int kn = kt + 2;
        if (kn < KT) issue(kn, kn % STAGES);
        asm volatile("cp.async.commit_group;" ::: "memory");

        const f16* sA = smem + stage * STAGE_ELEMS;
        const f16* sB = sA + A_ELEMS;
#pragma unroll
        for (int ks = 0; ks < 4; ks++) {
            const int kc = ks * 16;
            uint32_t af[4][4], bf[4][2];
#pragma unroll
            for (int i = 0; i < 4; i++)
                ldsm4(af[i], sptr(sA + a_off + (i & 1) * 16 * ROW_ELEMS
                                     + (i >> 1) * 32 * ROW_ELEMS + kc));
#pragma unroll
            for (int jj = 0; jj < 2; jj++) {
                uint32_t r[4];
                ldsm4(r, sptr(sB + b_off + jj * 16 * ROW_ELEMS + kc));
                bf[2 * jj][0] = r[0]; bf[2 * jj][1] = r[1];
                bf[2 * jj + 1][0] = r[2]; bf[2 * jj + 1][1] = r[3];
            }
#pragma unroll
            for (int i = 0; i < 4; i++)
#pragma unroll
                for (int j = 0; j < 4; j++)
                    mma_f16(acc[i][j], af[i], bf[j]);
        }
    }

    // ---------------- epilogue (alpha reduced in-CTA, deterministic) ----------------
    asm volatile("cp.async.wait_group 0;" ::: "memory");
    __syncthreads();
    const float alpha = reduce_alpha(reinterpret_cast<float*>(smem), sumLayer,
                                     sumParts, invCnt, tid);
    const int r0 = bm * TM + wm * 64 + (lane >> 2);
    const int c0 = bn * TN + wn * 32 + (lane & 3) * 2;
#pragma unroll
    for (int i = 0; i < 4; i++) {
#pragma unroll
        for (int j = 0; j < 4; j++) {
            int row = r0 + (i & 1) * 16 + (i >> 1) * 32;
            int col = c0 + j * 8;
            float bx = __ldg(bias + col), by = __ldg(bias + col + 1);
            float v00 = acc[i][j][0] * alpha + bx;
            float v01 = acc[i][j][1] * alpha + by;
            float v10 = acc[i][j][2] * alpha + bx;
            float v11 = acc[i][j][3] * alpha + by;
            if (EPI == 0) {
                v00 = fmaxf(v00, 0.f); v01 = fmaxf(v01, 0.f);
                v10 = fmaxf(v10, 0.f); v11 = fmaxf(v11, 0.f);
                size_t i0 = (size_t)row * N + col;
                size_t i1 = (size_t)(row + 8) * N + col;
                *reinterpret_cast<__half2*>(oH + i0) =
                    __halves2half2(__float2half(v00), __float2half(v01));
                *reinterpret_cast<__half2*>(oH + i1) =
                    __halves2half2(__float2half(v10), __float2half(v11));
            } else {
                float2 s0, s1;
                s0.x = 1.f / (1.f + __expf(-v00));
                s0.y = 1.f / (1.f + __expf(-v01));
                s1.x = 1.f / (1.f + __expf(-v10));
                s1.y = 1.f / (1.f + __expf(-v11));
                *reinterpret_cast<float2*>(oF + (size_t)row * N + col)       = s0;
                *reinterpret_cast<float2*>(oF + (size_t)(row + 8) * N + col) = s1;
            }
        }
    }
}

// ---------------- host launch ----------------
extern "C" void kernel_launch(void* const* d_in, const int* in_sizes, int n_in,
                              void* d_out, int out_size) {
    const float* x  = (const float*)d_in[0];
    const float* w1 = (const float*)d_in[1];
    const float* b1 = (const float*)d_in[2];
    const float* w2 = (const float*)d_in[3];
    const float* b2 = (const float*)d_in[4];
    const float* w3 = (const float*)d_in[5];
    const float* b3 = (const float*)d_in[6];

    void *pw1, *pw2, *pw3, *pa, *pb;
    cudaGetSymbolAddress(&pw1, g_w1s);
    cudaGetSymbolAddress(&pw2, g_w2s);
    cudaGetSymbolAddress(&pw3, g_w3s);
    cudaGetSymbolAddress(&pa, g_a);
    cudaGetSymbolAddress(&pb, g_b);

    cudaFuncSetAttribute(gemm_bwn<0>, cudaFuncAttributeMaxDynamicSharedMemorySize, SMEM_BYTES);
    cudaFuncSetAttribute(gemm_bwn<1>, cudaFuncAttributeMaxDynamicSharedMemorySize, SMEM_BYTES);

    // serial prefix: sign(w1) + convert(x); 1024 partials in g_part[0][0..1024)
    prep1_kernel<<<1024, 256>>>((const float4*)w1, (__half2*)pw1,
                                (const float4*)x, (__half2*)pa,
                                HIDDEN * IN_SIZE / 4, BATCH * IN_SIZE / 4);

    // GEMM1 (+ embedded sign(w2): 64 blocks at bn==32 write g_part[1][0..64))
    gemm_bwn<0><<<dim3(HIDDEN / TN + 1, BATCH / TM), 256, SMEM_BYTES>>>(
        (const f16*)pa, (const f16*)pw1, b1, 0, 1024,
        1.0f / ((float)HIDDEN * (float)IN_SIZE),
        IN_SIZE, HIDDEN, HIDDEN / TN, (f16*)pb, nullptr,
        (const float4*)w2, (__half2*)pw2, HIDDEN * HIDDEN / 4, 1);

    // GEMM2 (+ embedded sign(w3) -> g_part[2][0..64))
    gemm_bwn<0><<<dim3(HIDDEN / TN + 1, BATCH / TM), 256, SMEM_BYTES>>>(
        (const f16*)pb, (const f16*)pw2, b2, 1, BATCH / TM,
        1.0f / ((float)HIDDEN * (float)HIDDEN),
        HIDDEN, HIDDEN, HIDDEN / TN, (f16*)pa, nullptr,
        (const float4*)w3, (__half2*)pw3, OUT_SIZE * HIDDEN / 4, 2);

    // GEMM3 (no embedded prep)
    gemm_bwn<1><<<dim3(OUT_SIZE / TN, BATCH / TM), 256, SMEM_BYTES>>>(
        (const f16*)pa, (const f16*)pw3, b3, 2, BATCH / TM,
        1.0f / ((float)OUT_SIZE * (float)HIDDEN),
        HIDDEN, OUT_SIZE, OUT_SIZE / TN, nullptr, (float*)d_out,
        nullptr, nullptr, 0, 0);
}

// round 15
// speedup vs baseline: 1.0348x; 1.0117x over previous
#include <cuda_runtime.h>
#include <cuda_fp16.h>
#include <cstdint>

using f16 = __half;

// Problem dims
constexpr int BATCH    = 8192;
constexpr int IN_SIZE  = 4096;
constexpr int HIDDEN   = 4096;
constexpr int OUT_SIZE = 1024;

// GEMM tiling: CTA 128x128, warp tile 64x32 (2x4), BK=64, 2 CTAs/SM
constexpr int TM = 128;
constexpr int TN = 128;
constexpr int BK = 64;
constexpr int STAGES = 3;
constexpr int ROW_ELEMS  = 72;                    // 64 data + 8 pad f16 (144B pitch)
constexpr int A_ELEMS = TM * ROW_ELEMS;           // 9216
constexpr int B_ELEMS = TN * ROW_ELEMS;           // 9216
constexpr int STAGE_ELEMS = A_ELEMS + B_ELEMS;    // 18432
constexpr int SMEM_BYTES = STAGES * STAGE_ELEMS * 2;  // 110592 B -> 2 CTAs/SM

// ---------------- static device scratch ----------------
__device__ f16 g_w1s[HIDDEN * IN_SIZE];
__device__ f16 g_w2s[HIDDEN * HIDDEN];
__device__ f16 g_w3s[OUT_SIZE * HIDDEN];
__device__ f16 g_a[BATCH * IN_SIZE];
__device__ f16 g_b[BATCH * HIDDEN];
__device__ float g_part[3 * 2048];
__device__ float g_sum[3];

// ---------------- PTX helpers ----------------
__device__ __forceinline__ uint32_t sptr(const void* p) {
    return (uint32_t)__cvta_generic_to_shared(p);
}
__device__ __forceinline__ void cp16(const f16* dst_smem, const f16* src_gmem) {
    uint32_t d = sptr(dst_smem);
    asm volatile("cp.async.cg.shared.global [%0], [%1], 16;\n" :: "r"(d), "l"(src_gmem));
}
__device__ __forceinline__ void ldsm4(uint32_t* r, uint32_t addr) {
    asm volatile("ldmatrix.sync.aligned.m8n8.x4.shared.b16 {%0,%1,%2,%3}, [%4];"
                 : "=r"(r[0]), "=r"(r[1]), "=r"(r[2]), "=r"(r[3]) : "r"(addr));
}
__device__ __forceinline__ void mma_f16(float* d, const uint32_t* a, const uint32_t* b) {
    asm volatile(
        "mma.sync.aligned.m16n8k16.row.col.f32.f16.f16.f32 "
        "{%0,%1,%2,%3}, {%4,%5,%6,%7}, {%8,%9}, {%0,%1,%2,%3};"
        : "+f"(d[0]), "+f"(d[1]), "+f"(d[2]), "+f"(d[3])
        : "r"(a[0]), "r"(a[1]), "r"(a[2]), "r"(a[3]), "r"(b[0]), "r"(b[1]));
}

// ---------------- shared quant helper (sign -> f16, block partial |w| sums) ----------------
__device__ __forceinline__ void quant_signs(const float4* __restrict__ w4,
                                            __half2* __restrict__ ws2,
                                            int n4, int layer,
                                            int bid, int nblocks, int tid) {
    float s = 0.f;
    for (int i = bid * 256 + tid; i < n4; i += nblocks * 256) {
        float4 v = w4[i];
        s += fabsf(v.x) + fabsf(v.y) + fabsf(v.z) + fabsf(v.w);
        f16 s0 = __float2half((v.x > 0.f) ? 1.f : ((v.x < 0.f) ? -1.f : 0.f));
        f16 s1 = __float2half((v.y > 0.f) ? 1.f : ((v.y < 0.f) ? -1.f : 0.f));
        f16 s2 = __float2half((v.z > 0.f) ? 1.f : ((v.z < 0.f) ? -1.f : 0.f));
        f16 s3 = __float2half((v.w > 0.f) ? 1.f : ((v.w < 0.f) ? -1.f : 0.f));
        ws2[2 * i]     = __halves2half2(s0, s1);
        ws2[2 * i + 1] = __halves2half2(s2, s3);
    }
    __shared__ float red[256];
    red[tid] = s;
    __syncthreads();
    for (int o = 128; o > 0; o >>= 1) {
        if (tid < o) red[tid] += red[tid + o];
        __syncthreads();
    }
    if (tid == 0) g_part[layer * 2048 + bid] = red[0];
}

// ---------------- prep: sign(w1) + convert(x) fused ----------------
__global__ void prep1_kernel(const float4* __restrict__ w1,
                             __half2* __restrict__ w1s,
                             const float4* __restrict__ x4,
                             __half2* __restrict__ xh, int n4w, int n4x) {
    quant_signs(w1, w1s, n4w, 0, blockIdx.x, gridDim.x, threadIdx.x);
    for (int i = blockIdx.x * blockDim.x + threadIdx.x; i < n4x; i += gridDim.x * blockDim.x) {
        float4 v = x4[i];
        xh[2 * i]     = __halves2half2(__float2half(v.x), __float2half(v.y));
        xh[2 * i + 1] = __halves2half2(__float2half(v.z), __float2half(v.w));
    }
}

// reduce g_part[layer][0..nparts) -> g_sum[layer]  (layer 0 only)
__global__ void finalize_one_kernel(int layer, int nparts) {
    __shared__ float red[1024];
    int t = threadIdx.x;
    float s = 0.f;
    for (int i = t; i < nparts; i += 1024) s += g_part[layer * 2048 + i];
    red[t] = s;
    __syncthreads();
    for (int o = 512; o > 0; o >>= 1) {
        if (t < o) red[t] += red[t + o];
        __syncthreads();
    }
    if (t == 0) g_sum[layer] = red[0];
}

// ---------------- fused binarized GEMM + embedded next-layer weight quant ----------------
// alpha: if aParts > 0, every thread inline-sums g_part[aLayer][0..aParts) (barrier-free,
// deterministic, L2-broadcast); else read precomputed g_sum via sumAbs.
// EPI0: relu -> f16 ; EPI1: sigmoid -> f32
template <int EPI>
__global__ void __launch_bounds__(256, 2) gemm_bwn(
    const f16* __restrict__ A, const f16* __restrict__ Bs,
    const float* __restrict__ bias, const float* __restrict__ sumAbs,
    int aLayer, int aParts, float invCnt,
    int K, int N, int NB,
    f16* __restrict__ oH, float* __restrict__ oF,
    const float4* __restrict__ wsrc, __half2* __restrict__ wdst, int wn4, int wlayer) {
    extern __shared__ f16 smem[];
    const int tid  = threadIdx.x;

    if (blockIdx.x >= NB) {  // embedded prep path (next layer's weights)
        quant_signs(wsrc, wdst, wn4, wlayer, blockIdx.y, gridDim.y, tid);
        return;
    }

    const int lane = tid & 31;
    const int warp = tid >> 5;
    const int wm = warp & 1;   // 2 warp-rows of 64
    const int wn = warp >> 1;  // 4 warp-cols of 32
    const int bm = blockIdx.y, bn = blockIdx.x;
    const int KT = K / BK;

    const f16* gA = A  + (size_t)bm * TM * K;
    const f16* gB = Bs + (size_t)bn * TN * K;

    const int crow = tid >> 3;        // 0..31
    const int ccol = (tid & 7) * 8;   // 16B chunks

    auto issue = [&](int kt, int stage) {
        f16* sa = smem + stage * STAGE_ELEMS;
        f16* sb = sa + A_ELEMS;
        const int kof = kt * BK;
#pragma unroll
        for (int rr = 0; rr < 4; rr++) {
            const int row = rr * 32 + crow;
            cp16(sa + row * ROW_ELEMS + ccol, gA + (size_t)row * K + kof + ccol);
            cp16(sb + row * ROW_ELEMS + ccol, gB + (size_t)row * K + kof + ccol);
        }
    };

    float acc[4][4][4];
#pragma unroll
    for (int i = 0; i < 4; i++)
#pragma unroll
        for (int j = 0; j < 4; j++)
#pragma unroll
            for (int v = 0; v < 4; v++) acc[i][j][v] = 0.f;

    const int a_off = (wm * 64 + (lane & 15)) * ROW_ELEMS + (lane >> 4) * 8;
    const int b_off = (wn * 32 + ((lane >> 4) & 1) * 8 + (lane & 7)) * ROW_ELEMS
                    + ((lane >> 3) & 1) * 8;

    issue(0, 0);
    asm volatile("cp.async.commit_group;" ::: "memory");
    issue(1, 1);
    asm volatile("cp.async.commit_group;" ::: "memory");

    for (int kt = 0; kt < KT; kt++) {
        const int stage = kt % STAGES;
        asm volatile("cp.async.wait_group 1;" ::: "memory");
        __syncthreads();
        const int kn = kt + 2;
        if (kn < KT) issue(kn, kn % STAGES);
        asm volatile("cp.async.commit_group;" ::: "memory");

        const f16* sA = smem + stage * STAGE_ELEMS;
        const f16* sB = sA + A_ELEMS;
#pragma unroll
        for (int ks = 0; ks < 4; ks++) {
            const int kc = ks * 16;
            uint32_t af[4][4], bf[4][2];
#pragma unroll
            for (int i = 0; i < 4; i++)
                ldsm4(af[i], sptr(sA + a_off + (i & 1) * 16 * ROW_ELEMS
                                     + (i >> 1) * 32 * ROW_ELEMS + kc));
#pragma unroll
            for (int jj = 0; jj < 2; jj++) {
                uint32_t r[4];
                ldsm4(r, sptr(sB + b_off + jj * 16 * ROW_ELEMS + kc));
                bf[2 * jj][0] = r[0]; bf[2 * jj][1] = r[1];
                bf[2 * jj + 1][0] = r[2]; bf[2 * jj + 1][1] = r[3];
            }
#pragma unroll
            for (int i = 0; i < 4; i++)
#pragma unroll
                for (int j = 0; j < 4; j++)
                    mma_f16(acc[i][j], af[i], bf[j]);
        }
    }

    // ---------------- epilogue ----------------
    float alpha;
    if (aParts > 0) {
        // barrier-free redundant sum of 64 partials (deterministic linear order,
        // L2-broadcast hits, overlapped loads; no syncthreads, no smem)
        float s = 0.f;
        const float* p = g_part + aLayer * 2048;
#pragma unroll 16
        for (int i = 0; i < aParts; i++) s += __ldg(p + i);
        alpha = s * invCnt;
    } else {
        alpha = __ldg(sumAbs) * invCnt;
    }
    const int r0 = bm * TM + wm * 64 + (lane >> 2);
    const int c0 = bn * TN + wn * 32 + (lane & 3) * 2;
#pragma unroll
    for (int i = 0; i < 4; i++) {
#pragma unroll
        for (int j = 0; j < 4; j++) {
            int row = r0 + (i & 1) * 16 + (i >> 1) * 32;
            int col = c0 + j * 8;
            float bx = __ldg(bias + col), by = __ldg(bias + col + 1);
            float v00 = acc[i][j][0] * alpha + bx;
            float v01 = acc[i][j][1] * alpha + by;
            float v10 = acc[i][j][2] * alpha + bx;
            float v11 = acc[i][j][3] * alpha + by;
            if (EPI == 0) {
                v00 = fmaxf(v00, 0.f); v01 = fmaxf(v01, 0.f);
                v10 = fmaxf(v10, 0.f); v11 = fmaxf(v11, 0.f);
                size_t i0 = (size_t)row * N + col;
                size_t i1 = (size_t)(row + 8) * N + col;
                *reinterpret_cast<__half2*>(oH + i0) =
                    __halves2half2(__float2half(v00), __float2half(v01));
                *reinterpret_cast<__half2*>(oH + i1) =
                    __halves2half2(__float2half(v10), __float2half(v11));
            } else {
                float2 s0, s1;
                s0.x = 1.f / (1.f + __expf(-v00));
                s0.y = 1.f / (1.f + __expf(-v01));
                s1.x = 1.f / (1.f + __expf(-v10));
                s1.y = 1.f / (1.f + __expf(-v11));
                *reinterpret_cast<float2*>(oF + (size_t)row * N + col)       = s0;
                *reinterpret_cast<float2*>(oF + (size_t)(row + 8) * N + col) = s1;
            }
        }
    }
}

// ---------------- host launch ----------------
extern "C" void kernel_launch(void* const* d_in, const int* in_sizes, int n_in,
                              void* d_out, int out_size) {
    const float* x  = (const float*)d_in[0];
    const float* w1 = (const float*)d_in[1];
    const float* b1 = (const float*)d_in[2];
    const float* w2 = (const float*)d_in[3];
    const float* b2 = (const float*)d_in[4];
    const float* w3 = (const float*)d_in[5];
    const float* b3 = (const float*)d_in[6];

    void *pw1, *pw2, *pw3, *pa, *pb, *psum;
    cudaGetSymbolAddress(&pw1, g_w1s);
    cudaGetSymbolAddress(&pw2, g_w2s);
    cudaGetSymbolAddress(&pw3, g_w3s);
    cudaGetSymbolAddress(&pa, g_a);
    cudaGetSymbolAddress(&pb, g_b);
    cudaGetSymbolAddress(&psum, g_sum);
    float* sum = (float*)psum;

    cudaFuncSetAttribute(gemm_bwn<0>, cudaFuncAttributeMaxDynamicSharedMemorySize, SMEM_BYTES);
    cudaFuncSetAttribute(gemm_bwn<1>, cudaFuncAttributeMaxDynamicSharedMemorySize, SMEM_BYTES);

    // serial prefix: sign(w1) + convert(x), then finalize layer-0 sum (2048 partials)
    prep1_kernel<<<2048, 256>>>((const float4*)w1, (__half2*)pw1,
                                (const float4*)x, (__half2*)pa,
                                HIDDEN * IN_SIZE / 4, BATCH * IN_SIZE / 4);
    finalize_one_kernel<<<1, 1024>>>(0, 2048);

    // GEMM1 (+ embedded sign(w2): 64 blocks at bn==32 write g_part[1][0..64))
    gemm_bwn<0><<<dim3(HIDDEN / TN + 1, BATCH / TM), 256, SMEM_BYTES>>>(
        (const f16*)pa, (const f16*)pw1, b1, sum + 0, 0, 0,
        1.0f / ((float)HIDDEN * (float)IN_SIZE),
        IN_SIZE, HIDDEN, HIDDEN / TN, (f16*)pb, nullptr,
        (const float4*)w2, (__half2*)pw2, HIDDEN * HIDDEN / 4, 1);

    // GEMM2 (+ embedded sign(w3) -> g_part[2][0..64)); alpha = inline sum of 64 partials
    gemm_bwn<0><<<dim3(HIDDEN / TN + 1, BATCH / TM), 256, SMEM_BYTES>>>(
        (const f16*)pb, (const f16*)pw2, b2, nullptr, 1, BATCH / TM,
        1.0f / ((float)HIDDEN * (float)HIDDEN),
        HIDDEN, HIDDEN, HIDDEN / TN, (f16*)pa, nullptr,
        (const float4*)w3, (__half2*)pw3, OUT_SIZE * HIDDEN / 4, 2);

    // GEMM3 (no embedded prep); alpha = inline sum of 64 partials
    gemm_bwn<1><<<dim3(OUT_SIZE / TN, BATCH / TM), 256, SMEM_BYTES>>>(
        (const f16*)pa, (const f16*)pw3, b3, nullptr, 2, BATCH / TM,
        1.0f / ((float)OUT_SIZE * (float)HIDDEN),
        HIDDEN, OUT_SIZE, OUT_SIZE / TN, nullptr, (float*)d_out,
        nullptr, nullptr, 0, 0);
}

// round 16
// speedup vs baseline: 1.0506x; 1.0153x over previous
#include <cuda_runtime.h>
#include <cuda_fp16.h>
#include <cstdint>

using f16 = __half;

// Problem dims
constexpr int BATCH    = 8192;
constexpr int IN_SIZE  = 4096;
constexpr int HIDDEN   = 4096;
constexpr int OUT_SIZE = 1024;
constexpr int KDIM     = 4096;     // all GEMMs reduce over 4096
constexpr int KT       = KDIM / 64;

// GEMM tiling: CTA 128x128, warp tile 64x32 (2x4), BK=64, 2 CTAs/SM
constexpr int TM = 128;
constexpr int TN = 128;
constexpr int BK = 64;
constexpr int STAGES = 3;
constexpr int ROW_ELEMS  = 72;                    // 64 data + 8 pad f16 (144B pitch)
constexpr int A_ELEMS = TM * ROW_ELEMS;
constexpr int B_ELEMS = TN * ROW_ELEMS;
constexpr int STAGE_ELEMS = A_ELEMS + B_ELEMS;
constexpr int SMEM_BYTES = STAGES * STAGE_ELEMS * 2;  // 110592 -> 2 CTAs/SM

// fused grid layout
constexpr int NQ = 64;                       // quant blocks per weight matrix
constexpr int G1 = (BATCH / TM) * (HIDDEN / TN);    // 2048
constexpr int G2 = (BATCH / TM) * (HIDDEN / TN);    // 2048
constexpr int G3 = (BATCH / TM) * (OUT_SIZE / TN);  // 512
constexpr int G1BASE = 2 * NQ;
constexpr int G2BASE = G1BASE + G1;
constexpr int G3BASE = G2BASE + G2;
constexpr int GRID   = G3BASE + G3;          // 4736

// ---------------- static device scratch ----------------
__device__ f16 g_w1s[HIDDEN * IN_SIZE];
__device__ f16 g_w2s[HIDDEN * HIDDEN];
__device__ f16 g_w3s[OUT_SIZE * HIDDEN];
__device__ f16 g_a[BATCH * IN_SIZE];
__device__ f16 g_b[BATCH * HIDDEN];
__device__ float g_part[3 * 2048];
__device__ float g_sum0;
__device__ uint32_t g_cnt1[64];
__device__ uint32_t g_cnt2[64];
__device__ uint32_t g_cntW2;
__device__ uint32_t g_cntW3;

// ---------------- PTX helpers ----------------
__device__ __forceinline__ uint32_t sptr(const void* p) {
    return (uint32_t)__cvta_generic_to_shared(p);
}
__device__ __forceinline__ void cp16(const f16* dst_smem, const f16* src_gmem) {
    uint32_t d = sptr(dst_smem);
    asm volatile("cp.async.cg.shared.global [%0], [%1], 16;\n" :: "r"(d), "l"(src_gmem));
}
__device__ __forceinline__ void ldsm4(uint32_t* r, uint32_t addr) {
    asm volatile("ldmatrix.sync.aligned.m8n8.x4.shared.b16 {%0,%1,%2,%3}, [%4];"
                 : "=r"(r[0]), "=r"(r[1]), "=r"(r[2]), "=r"(r[3]) : "r"(addr));
}
__device__ __forceinline__ void mma_f16(float* d, const uint32_t* a, const uint32_t* b) {
    asm volatile(
        "mma.sync.aligned.m16n8k16.row.col.f32.f16.f16.f32 "
        "{%0,%1,%2,%3}, {%4,%5,%6,%7}, {%8,%9}, {%0,%1,%2,%3};"
        : "+f"(d[0]), "+f"(d[1]), "+f"(d[2]), "+f"(d[3])
        : "r"(a[0]), "r"(a[1]), "r"(a[2]), "r"(a[3]), "r"(b[0]), "r"(b[1]));
}
__device__ __forceinline__ void spin_ge(volatile uint32_t* p, uint32_t n) {
    while (*p < n) __nanosleep(200);
}

// ---------------- quant helper (sign -> f16, block partial |w| sums) ----------------
__device__ __forceinline__ void quant_signs(const float4* __restrict__ w4,
                                            __half2* __restrict__ ws2,
                                            int n4, int layer,
                                            int bid, int nblocks, int tid) {
    float s = 0.f;
    for (int i = bid * 256 + tid; i < n4; i += nblocks * 256) {
        float4 v = w4[i];
        s += fabsf(v.x) + fabsf(v.y) + fabsf(v.z) + fabsf(v.w);
        f16 s0 = __float2half((v.x > 0.f) ? 1.f : ((v.x < 0.f) ? -1.f : 0.f));
        f16 s1 = __float2half((v.y > 0.f) ? 1.f : ((v.y < 0.f) ? -1.f : 0.f));
        f16 s2 = __float2half((v.z > 0.f) ? 1.f : ((v.z < 0.f) ? -1.f : 0.f));
        f16 s3 = __float2half((v.w > 0.f) ? 1.f : ((v.w < 0.f) ? -1.f : 0.f));
        ws2[2 * i]     = __halves2half2(s0, s1);
        ws2[2 * i + 1] = __halves2half2(s2, s3);
    }
    __shared__ float red[256];
    red[tid] = s;
    __syncthreads();
    for (int o = 128; o > 0; o >>= 1) {
        if (tid < o) red[tid] += red[tid + o];
        __syncthreads();
    }
    if (tid == 0) g_part[layer * 2048 + bid] = red[0];
}

// ---------------- prep: sign(w1) + convert(x) + zero counters ----------------
__global__ void prep1_kernel(const float4* __restrict__ w1,
                             __half2* __restrict__ w1s,
                             const float4* __restrict__ x4,
                             __half2* __restrict__ xh, int n4w, int n4x) {
    if (blockIdx.x == 0) {
        if (threadIdx.x < 64) { g_cnt1[threadIdx.x] = 0; g_cnt2[threadIdx.x] = 0; }
        if (threadIdx.x == 0) { g_cntW2 = 0; g_cntW3 = 0; }
    }
    quant_signs(w1, w1s, n4w, 0, blockIdx.x, gridDim.x, threadIdx.x);
    for (int i = blockIdx.x * blockDim.x + threadIdx.x; i < n4x; i += gridDim.x * blockDim.x) {
        float4 v = x4[i];
        xh[2 * i]     = __halves2half2(__float2half(v.x), __float2half(v.y));
        xh[2 * i + 1] = __halves2half2(__float2half(v.z), __float2half(v.w));
    }
}

__global__ void finalize0_kernel() {
    __shared__ float red[1024];
    int t = threadIdx.x;
    float s = 0.f;
    for (int i = t; i < 2048; i += 1024) s += g_part[i];
    red[t] = s;
    __syncthreads();
    for (int o = 512; o > 0; o >>= 1) {
        if (t < o) red[t] += red[t + o];
        __syncthreads();
    }
    if (t == 0) g_sum0 = red[0];
}

// deterministic linear sum of 64 partials (same order everywhere)
__device__ __forceinline__ float sum64(const float* p) {
    float s = 0.f;
#pragma unroll 16
    for (int i = 0; i < 64; i++) s += __ldg(p + i);
    return s;
}

// ---------------- GEMM body (128x128 CTA, 64x32 warp tiles) ----------------
__device__ __forceinline__ void gemm_body(
    const f16* __restrict__ A, const f16* __restrict__ Bs,
    const float* __restrict__ bias, float alpha, int N, int bm, int bn,
    int epi, f16* __restrict__ oH, float* __restrict__ oF, f16* smem) {
    const int tid  = threadIdx.x;
    const int lane = tid & 31;
    const int warp = tid >> 5;
    const int wm = warp & 1;   // 2 warp-rows of 64
    const int wn = warp >> 1;  // 4 warp-cols of 32

    const f16* gA = A  + (size_t)bm * TM * KDIM;
    const f16* gB = Bs + (size_t)bn * TN * KDIM;

    const int crow = tid >> 3;
    const int ccol = (tid & 7) * 8;

    auto issue = [&](int kt, int stage) {
        f16* sa = smem + stage * STAGE_ELEMS;
        f16* sb = sa + A_ELEMS;
        const int kof = kt * BK;
#pragma unroll
        for (int rr = 0; rr < 4; rr++) {
            const int row = rr * 32 + crow;
            cp16(sa + row * ROW_ELEMS + ccol, gA + (size_t)row * KDIM + kof + ccol);
            cp16(sb + row * ROW_ELEMS + ccol, gB + (size_t)row * KDIM + kof + ccol);
        }
    };

    float acc[4][4][4];
#pragma unroll
    for (int i = 0; i < 4; i++)
#pragma unroll
        for (int j = 0; j < 4; j++)
#pragma unroll
            for (int v = 0; v < 4; v++) acc[i][j][v] = 0.f;

    const int a_off = (wm * 64 + (lane & 15)) * ROW_ELEMS + (lane >> 4) * 8;
    const int b_off = (wn * 32 + ((lane >> 4) & 1) * 8 + (lane & 7)) * ROW_ELEMS
                    + ((lane >> 3) & 1) * 8;

    issue(0, 0);
    asm volatile("cp.async.commit_group;" ::: "memory");
    issue(1, 1);
    asm volatile("cp.async.commit_group;" ::: "memory");

    for (int kt = 0; kt < KT; kt++) {
        const int stage = kt % STAGES;
        asm volatile("cp.async.wait_group 1;" ::: "memory");
        __syncthreads();
        const int kn = kt + 2;
        if (kn < KT) issue(kn, kn % STAGES);
        asm volatile("cp.async.commit_group;" ::: "memory");

        const f16* sA = smem + stage * STAGE_ELEMS;
        const f16* sB = sA + A_ELEMS;
#pragma unroll
        for (int ks = 0; ks < 4; ks++) {
            const int kc = ks * 16;
            uint32_t af[4][4], bf[4][2];
#pragma unroll
            for (int i = 0; i < 4; i++)
                ldsm4(af[i], sptr(sA + a_off + (i & 1) * 16 * ROW_ELEMS
                                     + (i >> 1) * 32 * ROW_ELEMS + kc));
#pragma unroll
            for (int jj = 0; jj < 2; jj++) {
                uint32_t r[4];
                ldsm4(r, sptr(sB + b_off + jj * 16 * ROW_ELEMS + kc));
                bf[2 * jj][0] = r[0]; bf[2 * jj][1] = r[1];
                bf[2 * jj + 1][0] = r[2]; bf[2 * jj + 1][1] = r[3];
            }
#pragma unroll
            for (int i = 0; i < 4; i++)
#pragma unroll
                for (int j = 0; j < 4; j++)
                    mma_f16(acc[i][j], af[i], bf[j]);
        }
    }

    const int r0 = bm * TM + wm * 64 + (lane >> 2);
    const int c0 = bn * TN + wn * 32 + (lane & 3) * 2;
#pragma unroll
    for (int i = 0; i < 4; i++) {
#pragma unroll
        for (int j = 0; j < 4; j++) {
            int row = r0 + (i & 1) * 16 + (i >> 1) * 32;
            int col = c0 + j * 8;
            float bx = __ldg(bias + col), by = __ldg(bias + col + 1);
            float v00 = acc[i][j][0] * alpha + bx;
            float v01 = acc[i][j][1] * alpha + by;
            float v10 = acc[i][j][2] * alpha + bx;
            float v11 = acc[i][j][3] * alpha + by;
            if (epi == 0) {
                v00 = fmaxf(v00, 0.f); v01 = fmaxf(v01, 0.f);
                v10 = fmaxf(v10, 0.f); v11 = fmaxf(v11, 0.f);
                size_t i0 = (size_t)row * N + col;
                size_t i1 = (size_t)(row + 8) * N + col;
                *reinterpret_cast<__half2*>(oH + i0) =
                    __halves2half2(__float2half(v00), __float2half(v01));
                *reinterpret_cast<__half2*>(oH + i1) =
                    __halves2half2(__float2half(v10), __float2half(v11));
            } else {
                float2 s0, s1;
                s0.x = 1.f / (1.f + __expf(-v00));
                s0.y = 1.f / (1.f + __expf(-v01));
                s1.x = 1.f / (1.f + __expf(-v10));
                s1.y = 1.f / (1.f + __expf(-v11));
                *reinterpret_cast<float2*>(oF + (size_t)row * N + col)       = s0;
                *reinterpret_cast<float2*>(oF + (size_t)(row + 8) * N + col) = s1;
            }
        }
    }
}

// ---------------- fused mega-kernel: quant(w2,w3) + GEMM1 + GEMM2 + GEMM3 ----------------
__global__ void __launch_bounds__(256, 2) fused_kernel(
    const float4* __restrict__ w2src, const float4* __restrict__ w3src,
    const float* __restrict__ b1, const float* __restrict__ b2,
    const float* __restrict__ b3, float* __restrict__ dout) {
    extern __shared__ f16 smem[];
    const int bid = blockIdx.x;
    const int tid = threadIdx.x;

    if (bid < NQ) {  // quant w2
        quant_signs(w2src, (__half2*)g_w2s, HIDDEN * HIDDEN / 4, 1, bid, NQ, tid);
        __threadfence();
        __syncthreads();
        if (tid == 0) atomicAdd(&g_cntW2, 1u);
        return;
    }
    if (bid < 2 * NQ) {  // quant w3
        quant_signs(w3src, (__half2*)g_w3s, OUT_SIZE * HIDDEN / 4, 2, bid - NQ, NQ, tid);
        __threadfence();
        __syncthreads();
        if (tid == 0) atomicAdd(&g_cntW3, 1u);
        return;
    }
    if (bid < G2BASE) {  // GEMM1: x @ w1s
        const int idx = bid - G1BASE;
        const int bn = idx & 31, bm = idx >> 5;
        const float alpha = __ldg(&g_sum0) * (1.0f / ((float)HIDDEN * (float)IN_SIZE));
        gemm_body(g_a, g_w1s, b1, alpha, HIDDEN, bm, bn, 0, g_b, nullptr, smem);
        __threadfence();
        __syncthreads();
        if (tid == 0) atomicAdd(&g_cnt1[bm], 1u);
        return;
    }
    if (bid < G3BASE) {  // GEMM2: h1 @ w2s
        const int idx = bid - G2BASE;
        const int bn = idx & 31, bm = idx >> 5;
        if (tid == 0) {
            spin_ge(&g_cntW2, NQ);
            spin_ge(&g_cnt1[bm], 32);
        }
        __syncthreads();
        __threadfence();
        const float alpha = sum64(g_part + 2048) * (1.0f / ((float)HIDDEN * (float)HIDDEN));
        gemm_body(g_b, g_w2s, b2, alpha, HIDDEN, bm, bn, 0, g_a, nullptr, smem);
        __threadfence();
        __syncthreads();
        if (tid == 0) atomicAdd(&g_cnt2[bm], 1u);
        return;
    }
    {  // GEMM3: h2 @ w3s -> sigmoid f32
        const int idx = bid - G3BASE;
        const int bn = idx & 7, bm = idx >> 3;
        if (tid == 0) {
            spin_ge(&g_cntW3, NQ);
            spin_ge(&g_cnt2[bm], 32);
        }
        __syncthreads();
        __threadfence();
        const float alpha = sum64(g_part + 4096) * (1.0f / ((float)OUT_SIZE * (float)HIDDEN));
        gemm_body(g_a, g_w3s, b3, alpha, OUT_SIZE, bm, bn, 1, nullptr, dout, smem);
    }
}

// ---------------- host launch ----------------
extern "C" void kernel_launch(void* const* d_in, const int* in_sizes, int n_in,
                              void* d_out, int out_size) {
    const float* x  = (const float*)d_in[0];
    const float* w1 = (const float*)d_in[1];
    const float* b1 = (const float*)d_in[2];
    const float* w2 = (const float*)d_in[3];
    const float* b2 = (const float*)d_in[4];
    const float* w3 = (const float*)d_in[5];
    const float* b3 = (const float*)d_in[6];

    void *pw1, *pa;
    cudaGetSymbolAddress(&pw1, g_w1s);
    cudaGetSymbolAddress(&pa, g_a);

    cudaFuncSetAttribute(fused_kernel, cudaFuncAttributeMaxDynamicSharedMemorySize, SMEM_BYTES);

    // serial prefix: sign(w1) + convert(x) + zero counters, then layer-0 sum
    prep1_kernel<<<2048, 256>>>((const float4*)w1, (__half2*)pw1,
                                (const float4*)x, (__half2*)pa,
                                HIDDEN * IN_SIZE / 4, BATCH * IN_SIZE / 4);
    finalize0_kernel<<<1, 1024>>>();

    // everything else: one fused, self-synchronizing grid
    fused_kernel<<<GRID, 256, SMEM_BYTES>>>(
        (const float4*)w2, (const float4*)w3, b1, b2, b3, (float*)d_out);
}